// round 15
// baseline (speedup 1.0000x reference)
#include <cuda_runtime.h>
#include <math.h>
#include <stdint.h>

// VolatilityLoss: mean((std3(pred) - std3(targ))^2), window w=3.
// B=512, S=8192, L=8190 outputs/row.
// SINGLE-WAVE persistent kernel: 512 CTAs (one per row) x 256 threads.
// Row processed as 4 chunks of 2048 elems through 2 double-buffered SMEM
// buffers (33KB -> 6 CTAs/SM -> capacity 888 >= 512 = one wave).
// Prologue issues chunks 0,1; loop: wait c, compute c, sync, issue c+2.
// Packed-f32x2 rolling chain; 6*var_i = e_i^2+e_{i+1}^2+(e_i+e_{i+1})^2;
// pair via one sqrt; deferred /6.

#define B_ROWS 512
#define S_LEN  8192
#define L_OUT  (S_LEN - 2)
#define NBLOCKS 512           // one per row
#define NTHREADS 256
#define CHUNK 2048            // elements per chunk per array
#define EXTRA 16              // peek elements (chunks 0-2 only)
#define NCHUNKS 4

typedef unsigned long long u64;

__device__ float        g_partials[NBLOCKS];
__device__ unsigned int g_counter = 0;   // monotone across graph replays

__device__ __forceinline__ float sqrt_approx(float x) {
    float r;
    asm("sqrt.approx.f32 %0, %1;" : "=f"(r) : "f"(x));
    return r;
}

__device__ __forceinline__ uint32_t smem_u32(const void* p) {
    uint32_t a;
    asm("{ .reg .u64 t; cvta.to.shared.u64 t, %1; cvt.u32.u64 %0, t; }"
        : "=r"(a) : "l"(p));
    return a;
}

__device__ __forceinline__ void mbar_wait(uint32_t mbar, uint32_t parity) {
    asm volatile(
        "{\n\t.reg .pred P;\n"
        "W%=:\n\t"
        "mbarrier.try_wait.parity.acquire.cta.shared::cta.b64 P, [%0], %1, 0x989680;\n\t"
        "@!P bra W%=;\n\t}"
        :: "r"(mbar), "r"(parity) : "memory");
}

__device__ __forceinline__ void issue_chunk(uint32_t mbar,
                                            float* sp, float* sq,
                                            const float* pg, const float* tg,
                                            int c) {
    const uint32_t bytes = (c < NCHUNKS - 1 ? CHUNK + EXTRA : CHUNK) * 4u;
    asm volatile("mbarrier.arrive.expect_tx.shared::cta.b64 _, [%0], %1;"
                 :: "r"(mbar), "r"(bytes * 2u) : "memory");
    asm volatile(
        "cp.async.bulk.shared::cluster.global.mbarrier::complete_tx::bytes "
        "[%0], [%1], %2, [%3];"
        :: "r"(smem_u32(sp)), "l"(pg + c * CHUNK), "r"(bytes), "r"(mbar)
        : "memory");
    asm volatile(
        "cp.async.bulk.shared::cluster.global.mbarrier::complete_tx::bytes "
        "[%0], [%1], %2, [%3];"
        :: "r"(smem_u32(sq)), "l"(tg + c * CHUNK), "r"(bytes), "r"(mbar)
        : "memory");
}

#define PACK2(dst, lo, hi) \
    asm("mov.b64 %0, {%1, %2};" : "=l"(dst) : "f"(lo), "f"(hi))
#define UNPACK2(lo, hi, src) \
    asm("mov.b64 {%0, %1}, %2;" : "=f"(lo), "=f"(hi) : "l"(src))
#define FMA2(dst, a, b, c) \
    asm("fma.rn.f32x2 %0, %1, %2, %3;" : "=l"(dst) : "l"(a), "l"(b), "l"(c))
#define ADD2(dst, a, b) \
    asm("add.rn.f32x2 %0, %1, %2;" : "=l"(dst) : "l"(a), "l"(b))
#define MUL2(dst, a, b) \
    asm("mul.rn.f32x2 %0, %1, %2;" : "=l"(dst) : "l"(a), "l"(b))

// Consume one element pair; completes the window ending 2 elems back (if v).
#define STEP(pel, tel, v)                                   \
    do {                                                    \
        u64 Pn, E, Gc, F, GS, V;                            \
        PACK2(Pn, pel, tel);                                \
        FMA2(E, Pn, M1, Pc);      /* E = Pc - Pn */         \
        MUL2(Gc, E, E);                                     \
        ADD2(F, Ep, E);                                     \
        ADD2(GS, Gp, Gc);                                   \
        FMA2(V, F, F, GS);        /* {6vp, 6vt} >= 0 */     \
        if (v) {                                            \
            ADD2(accV, accV, V);                            \
            float _vp, _vt;                                 \
            UNPACK2(_vp, _vt, V);                           \
            accR += sqrt_approx(_vp * _vt);                 \
        }                                                   \
        Ep = E; Gp = Gc; Pc = Pn;                           \
    } while (0)

__global__ void __launch_bounds__(NTHREADS)
vol_loss_tma(const float* __restrict__ pred, const float* __restrict__ targ,
             float* __restrict__ out) {
    __shared__ alignas(16) float sp[2][CHUNK + EXTRA];
    __shared__ alignas(16) float sq[2][CHUNK + EXTRA];
    __shared__ alignas(8)  u64   mbar_store[2];
    __shared__ float red[NTHREADS / 32];
    __shared__ bool  is_last;

    const int t = threadIdx.x;
    const float* pg = pred + ((size_t)blockIdx.x << 13);
    const float* tg = targ + ((size_t)blockIdx.x << 13);
    const uint32_t mb0 = smem_u32(&mbar_store[0]);
    const uint32_t mb1 = smem_u32(&mbar_store[1]);

    if (t == 0) {
        asm volatile("mbarrier.init.shared::cta.b64 [%0], 1;" :: "r"(mb0) : "memory");
        asm volatile("mbarrier.init.shared::cta.b64 [%0], 1;" :: "r"(mb1) : "memory");
    }
    __syncthreads();

    if (t == 0) {
        issue_chunk(mb0, sp[0], sq[0], pg, tg, 0);
        issue_chunk(mb1, sp[1], sq[1], pg, tg, 1);
    }

    u64 M1, accV;
    PACK2(M1,   -1.0f, -1.0f);
    PACK2(accV,  0.0f,  0.0f);
    float accR = 0.0f;

    #pragma unroll
    for (int c = 0; c < NCHUNKS; ++c) {
        const int buf    = c & 1;
        const int parity = (c >> 1) & 1;
        mbar_wait(buf ? mb1 : mb0, parity);

        // Compute chunk c: 2 passes x 4 windows/thread. For chunk 3 the peek
        // region holds stale chunk-1 data — those windows are predicated off
        // (gw >= L_OUT) and never accumulated.
        const float* bp = sp[buf];
        const float* bq = sq[buf];
        #pragma unroll
        for (int p = 0; p < 2; ++p) {
            const int idx = p * (NTHREADS * 4) + (t << 2);
            float4 P  = *(const float4*)&bp[idx];
            float4 T  = *(const float4*)&bq[idx];
            float2 Pp = *(const float2*)&bp[idx + 4];
            float2 Tp = *(const float2*)&bq[idx + 4];
            const int gw = c * CHUNK + idx;

            u64 P0, Pc, Ep, Gp;
            PACK2(P0, P.x, T.x);
            PACK2(Pc, P.y, T.y);
            FMA2(Ep, Pc, M1, P0);
            MUL2(Gp, Ep, Ep);
            STEP(P.z,  T.z,  (gw + 0) < L_OUT);
            STEP(P.w,  T.w,  (gw + 1) < L_OUT);
            STEP(Pp.x, Tp.x, (gw + 2) < L_OUT);
            STEP(Pp.y, Tp.y, (gw + 3) < L_OUT);
        }

        if (c + 2 < NCHUNKS) {
            __syncthreads();   // everyone done reading this buffer
            if (t == 0)
                issue_chunk(buf ? mb1 : mb0, sp[buf], sq[buf], pg, tg, c + 2);
        }
    }

    float vps, vts;
    UNPACK2(vps, vts, accV);
    float acc = (vps + vts) - 2.0f * accR;   // still scaled by 6

    // Deterministic intra-block reduction.
    const int lane = t & 31;
    #pragma unroll
    for (int o = 16; o > 0; o >>= 1)
        acc += __shfl_down_sync(0xffffffffu, acc, o);
    if (lane == 0) red[t >> 5] = acc;
    __syncthreads();

    if (t == 0) {
        float v = 0.0f;
        #pragma unroll
        for (int w = 0; w < NTHREADS / 32; ++w) v += red[w];
        g_partials[blockIdx.x] = v;
        __threadfence();
        unsigned int old = atomicAdd(&g_counter, 1u);
        is_last = ((old + 1u) % (unsigned)NBLOCKS) == 0u;
    }
    __syncthreads();

    if (!is_last) return;

    // Last-arriving block: deterministic final reduction; fold deferred /6.
    __shared__ double sh[NTHREADS];
    double s = 0.0;
    for (int i = t; i < NBLOCKS; i += NTHREADS)
        s += (double)g_partials[i];
    sh[t] = s;
    __syncthreads();
    #pragma unroll
    for (int stride = NTHREADS / 2; stride > 0; stride >>= 1) {
        if (t < stride) sh[t] += sh[t + stride];
        __syncthreads();
    }
    if (t == 0)
        out[0] = (float)(sh[0] / (6.0 * (double)B_ROWS * (double)L_OUT));
}

extern "C" void kernel_launch(void* const* d_in, const int* in_sizes, int n_in,
                              void* d_out, int out_size) {
    const float* pred = (const float*)d_in[0];
    const float* targ = (const float*)d_in[1];
    vol_loss_tma<<<NBLOCKS, NTHREADS>>>(pred, targ, (float*)d_out);
}